// round 8
// baseline (speedup 1.0000x reference)
#include <cuda_runtime.h>
#include <cuda_bf16.h>
#include <cuda_fp16.h>
#include <math.h>
#include <stdint.h>

#define DD   128
#define MAXN 50000
#define MAXE 800000

// Scratch (allocation-free rule: __device__ globals)
__device__ __align__(16) float   g_dinv[MAXN];
__device__ __align__(16) __half  g_hbuf[(size_t)MAXN * DD];  // fp16 messages
__device__ __align__(16) float   g_buf2[(size_t)MAXN * DD];  // fp32 activation
__device__ __align__(16) int     g_cnt[MAXN];
__device__ __align__(16) int     g_rowptr[MAXN + 4];
__device__ __align__(16) int     g_cur[MAXN];
__device__ __align__(16) int     g_col[MAXE];
__device__ __align__(16) int     g_part[64];
// Pre-split/transposed/swizzled W image:
// [kh0: Bhi 16KB | Blo 16KB][kh1: Bhi 16KB | Blo 16KB]  (Bt[n][k] bf16, SW128)
__device__ __align__(16) uint8_t g_wb[65536];

// ---------------------------------------------------------------------------
// Helpers (sm_80+ only: ldmatrix + mma.sync — NO tcgen05, target is sm_103)
// ---------------------------------------------------------------------------
__device__ __forceinline__ uint32_t swz128(uint32_t off) {
    return off ^ ((off >> 3) & 0x70);
}
__device__ __forceinline__ uint32_t smem_u32(const void* p) {
    return (uint32_t)__cvta_generic_to_shared(p);
}

__device__ __forceinline__ void ldsm_x4(uint32_t& r0, uint32_t& r1,
                                        uint32_t& r2, uint32_t& r3, uint32_t addr) {
    asm volatile("ldmatrix.sync.aligned.m8n8.x4.shared.b16 {%0,%1,%2,%3}, [%4];"
                 : "=r"(r0), "=r"(r1), "=r"(r2), "=r"(r3) : "r"(addr));
}
__device__ __forceinline__ void ldsm_x2(uint32_t& r0, uint32_t& r1, uint32_t addr) {
    asm volatile("ldmatrix.sync.aligned.m8n8.x2.shared.b16 {%0,%1}, [%2];"
                 : "=r"(r0), "=r"(r1) : "r"(addr));
}
__device__ __forceinline__ void mma_bf16(float& d0, float& d1, float& d2, float& d3,
                                         uint32_t a0, uint32_t a1, uint32_t a2, uint32_t a3,
                                         uint32_t b0, uint32_t b1) {
    asm volatile(
        "mma.sync.aligned.m16n8k16.row.col.f32.bf16.bf16.f32 "
        "{%0,%1,%2,%3}, {%4,%5,%6,%7}, {%8,%9}, {%0,%1,%2,%3};"
        : "+f"(d0), "+f"(d1), "+f"(d2), "+f"(d3)
        : "r"(a0), "r"(a1), "r"(a2), "r"(a3), "r"(b0), "r"(b1));
}

// ---------------------------------------------------------------------------
// Histogram of dst (4 edges per thread)
// ---------------------------------------------------------------------------
__global__ void k_hist(const int* __restrict__ dst, int* __restrict__ cnt, int E) {
    int i = (blockIdx.x * blockDim.x + threadIdx.x) * 4;
    if (i + 3 < E && ((((size_t)dst) & 15) == 0)) {
        int4 d = *(const int4*)(dst + i);
        atomicAdd(&cnt[d.x], 1);
        atomicAdd(&cnt[d.y], 1);
        atomicAdd(&cnt[d.z], 1);
        atomicAdd(&cnt[d.w], 1);
    } else {
        for (int j = 0; j < 4; j++)
            if (i + j < E) atomicAdd(&cnt[dst[i + j]], 1);
    }
}

// ---------------------------------------------------------------------------
// 2-phase exclusive scan (+ dinv epilogue). Phase 1: per-block (1024) sums.
// ---------------------------------------------------------------------------
__global__ __launch_bounds__(256) void k_scan_partial(const int* __restrict__ cnt,
                                                      int* __restrict__ part, int n) {
    __shared__ int sh[8];
    int tid  = threadIdx.x;
    int base = blockIdx.x * 1024 + tid * 4;
    int s = 0;
    if (base + 3 < n) {
        int4 v = *(const int4*)(cnt + base);
        s = v.x + v.y + v.z + v.w;
    } else {
        for (int j = 0; j < 4; j++)
            if (base + j < n) s += cnt[base + j];
    }
#pragma unroll
    for (int o = 16; o; o >>= 1) s += __shfl_down_sync(0xffffffffu, s, o);
    if ((tid & 31) == 0) sh[tid >> 5] = s;
    __syncthreads();
    if (tid < 8) {
        s = sh[tid];
#pragma unroll
        for (int o = 4; o; o >>= 1) s += __shfl_down_sync(0x000000ffu, s, o);
        if (tid == 0) part[blockIdx.x] = s;
    }
}

// Phase 2 (fused tops-scan): every block redundantly scans the <=64 partials
// in-register, takes its own exclusive offset, then does the downsweep.
__global__ __launch_bounds__(256) void k_scan_down(const int* __restrict__ cnt,
                                                   const int* __restrict__ part,
                                                   int* __restrict__ rowptr,
                                                   int* __restrict__ cur,
                                                   float* __restrict__ dinv,
                                                   int n, int nb) {
    __shared__ int wsum[8];
    __shared__ int porig[64];   // raw partials
    __shared__ int pincl[64];   // per-warp inclusive scan of partials
    int tid  = threadIdx.x;
    int lane = tid & 31, wid = tid >> 5;

    if (tid < 64) {
        int v = (tid < nb) ? part[tid] : 0;
        porig[tid] = v;
        int x = v;
#pragma unroll
        for (int o = 1; o < 32; o <<= 1) {
            int u = __shfl_up_sync(0xffffffffu, x, o);
            if (lane >= o) x += u;
        }
        pincl[tid] = x;
    }
    __syncthreads();
    // exclusive offset for this block: incl(bi) - part[bi], where
    // incl(i) = pincl[i] + (i>=32 ? pincl[31] : 0)
    int bi = blockIdx.x;
    int bincl = pincl[bi] + ((bi >= 32) ? pincl[31] : 0);
    int bexc  = bincl - porig[bi];
    // last block writes the grand total to rowptr[n]
    if (bi == nb - 1 && tid == 0) rowptr[n] = bincl;

    int base = bi * 1024 + tid * 4;

    int4 c = make_int4(0, 0, 0, 0);
    if (base + 3 < n) c = *(const int4*)(cnt + base);
    else {
        int* cp = (int*)&c;
        for (int j = 0; j < 4; j++) cp[j] = (base + j < n) ? cnt[base + j] : 0;
    }
    int s0 = c.x, s1 = s0 + c.y, s2 = s1 + c.z, s3 = s2 + c.w;
    int ts = s3, sc = ts;
#pragma unroll
    for (int o = 1; o < 32; o <<= 1) {
        int u = __shfl_up_sync(0xffffffffu, sc, o);
        if (lane >= o) sc += u;
    }
    if (lane == 31) wsum[wid] = sc;
    __syncthreads();
    if (wid == 0) {
        int w = (lane < 8) ? wsum[lane] : 0;
#pragma unroll
        for (int o = 1; o < 8; o <<= 1) {
            int u = __shfl_up_sync(0xffffffffu, w, o);
            if (lane >= o) w += u;
        }
        if (lane < 8) wsum[lane] = w;
    }
    __syncthreads();

    int off = bexc + (wid ? wsum[wid - 1] : 0) + (sc - ts);
    if (base + 3 < n) {
        int4 r = make_int4(off, off + s0, off + s1, off + s2);
        *(int4*)(rowptr + base) = r;
        *(int4*)(cur + base)    = r;
        float4 dv = make_float4(rsqrtf((float)(c.x + 1)), rsqrtf((float)(c.y + 1)),
                                rsqrtf((float)(c.z + 1)), rsqrtf((float)(c.w + 1)));
        *(float4*)(dinv + base) = dv;
    } else {
        int rr[4] = {off, off + s0, off + s1, off + s2};
        int* cp = (int*)&c;
        for (int j = 0; j < 4; j++)
            if (base + j < n) {
                rowptr[base + j] = rr[j];
                cur[base + j]    = rr[j];
                dinv[base + j]   = rsqrtf((float)(cp[j] + 1));
            }
    }
}

// ---------------------------------------------------------------------------
// CSR fill
// ---------------------------------------------------------------------------
__global__ void k_fill(const int* __restrict__ src, const int* __restrict__ dst,
                       int* __restrict__ cur, int* __restrict__ col, int E) {
    int i = (blockIdx.x * blockDim.x + threadIdx.x) * 4;
    if (i + 3 < E && ((((size_t)src) & 15) == 0) && ((((size_t)dst) & 15) == 0)) {
        int4 s = *(const int4*)(src + i);
        int4 d = *(const int4*)(dst + i);
        col[atomicAdd(&cur[d.x], 1)] = s.x;
        col[atomicAdd(&cur[d.y], 1)] = s.y;
        col[atomicAdd(&cur[d.z], 1)] = s.z;
        col[atomicAdd(&cur[d.w], 1)] = s.w;
    } else {
        for (int j = 0; j < 4; j++)
            if (i + j < E) col[atomicAdd(&cur[dst[i + j]], 1)] = src[i + j];
    }
}

// ---------------------------------------------------------------------------
// W prep: split fp32 W[k][n] into bf16 hi/lo, transposed to Bt[n][k] K-major,
// SW128-swizzled, two K-halves. Layout matches the GEMM smem B image exactly.
// ---------------------------------------------------------------------------
__global__ void k_wprep(const float* __restrict__ W, uint8_t* __restrict__ wb) {
    int idx = blockIdx.x * blockDim.x + threadIdx.x;   // 0..16383
    int nn = idx & 127;           // output col -> Bt row
    int k  = idx >> 7;            // input dim  -> Bt col
    float v = W[k * DD + nn];
    __nv_bfloat16 hi = __float2bfloat16(v);
    __nv_bfloat16 lo = __float2bfloat16(v - __bfloat162float(hi));
    int half = k >> 6, kk = k & 63;
    uint32_t off = swz128((uint32_t)(nn * 128 + kk * 2));
    *(__nv_bfloat16*)(wb + half * 32768 + off)         = hi;
    *(__nv_bfloat16*)(wb + half * 32768 + 16384 + off) = lo;
}

// ---------------------------------------------------------------------------
// Tensor-core GEMM via mma.sync (split bf16, fp32 accum), fp16 output:
//   Ch[r,:] = (half) dinv[r] * (A[r,:] @ W)
// ---------------------------------------------------------------------------
static const uint32_t GEMM_SMEM = 65536;

__global__ void __launch_bounds__(256)
k_gemm_mma(const float* __restrict__ A, const uint8_t* __restrict__ wb,
           const float* __restrict__ dinv, __half* __restrict__ Ch, int n) {
    extern __shared__ char sm[];
    uint32_t sbase = smem_u32(sm);
    int tid  = threadIdx.x;
    int wid  = tid >> 5, lane = tid & 31;
    int row0 = blockIdx.x * 128;

    int mrow0 = (wid & 3) * 32;      // warp row base within tile
    int ncol0 = (wid >> 2) * 64;     // warp col base within tile

    float acc[2][8][4];
#pragma unroll
    for (int i = 0; i < 2; i++)
#pragma unroll
        for (int j = 0; j < 8; j++)
#pragma unroll
            for (int q = 0; q < 4; q++) acc[i][j][q] = 0.0f;

    const float4* A4 = (const float4*)A;

    for (int kh = 0; kh < 2; kh++) {
        // ---- stage B: 32KB pre-baked copy
        const float4* wb4 = (const float4*)(wb + kh * 32768);
#pragma unroll
        for (int t = 0; t < 8; t++) {
            int i = tid + t * 256;                     // 0..2047 float4
            *(float4*)(sm + 32768 + i * 16) = wb4[i];
        }
        // ---- stage A: load fp32, split to bf16 hi/lo, swizzled store
#pragma unroll
        for (int t = 0; t < 8; t++) {
            int i  = tid + t * 256;                    // 0..2047
            int m  = i >> 4;                           // row in tile
            int f4 = i & 15;                           // float4 idx in 64-k half
            int gr = row0 + m;
            float4 v = (gr < n) ? A4[(size_t)gr * 32 + kh * 16 + f4]
                                : make_float4(0.f, 0.f, 0.f, 0.f);
            __nv_bfloat16 hx = __float2bfloat16(v.x);
            __nv_bfloat16 hy = __float2bfloat16(v.y);
            __nv_bfloat16 hz = __float2bfloat16(v.z);
            __nv_bfloat16 hw = __float2bfloat16(v.w);
            __nv_bfloat162 h0, h1, l0, l1;
            h0.x = hx; h0.y = hy; h1.x = hz; h1.y = hw;
            l0.x = __float2bfloat16(v.x - __bfloat162float(hx));
            l0.y = __float2bfloat16(v.y - __bfloat162float(hy));
            l1.x = __float2bfloat16(v.z - __bfloat162float(hz));
            l1.y = __float2bfloat16(v.w - __bfloat162float(hw));
            uint32_t off = swz128((uint32_t)(m * 128 + f4 * 8));
            *(__nv_bfloat162*)(sm + off)             = h0;
            *(__nv_bfloat162*)(sm + off + 4)         = h1;
            *(__nv_bfloat162*)(sm + 16384 + off)     = l0;
            *(__nv_bfloat162*)(sm + 16384 + off + 4) = l1;
        }
        __syncthreads();

        // ---- MMA over 4 k16 steps in this half
#pragma unroll
        for (int k16 = 0; k16 < 4; k16++) {
            int kbyte = k16 * 32;
            uint32_t afh[2][4], afl[2][4];
#pragma unroll
            for (int mt = 0; mt < 2; mt++) {
                int mrow = mrow0 + mt * 16 + (lane & 7) + ((lane & 8) ? 8 : 0);
                int kb   = kbyte + ((lane & 16) ? 16 : 0);
                uint32_t a = sbase + swz128((uint32_t)(mrow * 128 + kb));
                ldsm_x4(afh[mt][0], afh[mt][1], afh[mt][2], afh[mt][3], a);
                ldsm_x4(afl[mt][0], afl[mt][1], afl[mt][2], afl[mt][3], a + 16384);
            }
#pragma unroll
            for (int nt = 0; nt < 8; nt++) {
                int nrow = ncol0 + nt * 8 + (lane & 7);
                int kb   = kbyte + ((lane & 8) ? 16 : 0);
                uint32_t baddr = sbase + 32768 + swz128((uint32_t)(nrow * 128 + kb));
                uint32_t bh0, bh1, bl0, bl1;
                ldsm_x2(bh0, bh1, baddr);
                ldsm_x2(bl0, bl1, baddr + 16384);
#pragma unroll
                for (int mt = 0; mt < 2; mt++) {
                    mma_bf16(acc[mt][nt][0], acc[mt][nt][1], acc[mt][nt][2], acc[mt][nt][3],
                             afh[mt][0], afh[mt][1], afh[mt][2], afh[mt][3], bh0, bh1);
                    mma_bf16(acc[mt][nt][0], acc[mt][nt][1], acc[mt][nt][2], acc[mt][nt][3],
                             afh[mt][0], afh[mt][1], afh[mt][2], afh[mt][3], bl0, bl1);
                    mma_bf16(acc[mt][nt][0], acc[mt][nt][1], acc[mt][nt][2], acc[mt][nt][3],
                             afl[mt][0], afl[mt][1], afl[mt][2], afl[mt][3], bh0, bh1);
                }
            }
        }
        __syncthreads();
    }

    // ---- epilogue: dinv scale + fp16 store
#pragma unroll
    for (int mt = 0; mt < 2; mt++) {
        int r1 = row0 + mrow0 + mt * 16 + (lane >> 2);
        int r2 = r1 + 8;
        float s1 = (r1 < n) ? dinv[r1] : 0.f;
        float s2 = (r2 < n) ? dinv[r2] : 0.f;
#pragma unroll
        for (int nt = 0; nt < 8; nt++) {
            int col = ncol0 + nt * 8 + ((lane & 3) << 1);
            if (r1 < n)
                *(__half2*)(Ch + (size_t)r1 * DD + col) =
                    __floats2half2_rn(acc[mt][nt][0] * s1, acc[mt][nt][1] * s1);
            if (r2 < n)
                *(__half2*)(Ch + (size_t)r2 * DD + col) =
                    __floats2half2_rn(acc[mt][nt][2] * s2, acc[mt][nt][3] * s2);
        }
    }
}

// ---------------------------------------------------------------------------
// Fused CSR gather + self-loop + bias + ELU. One warp per dst node.
// fp16 messages in, fp32 accumulate, fp32 out. Lane l owns 4 halves (uint2).
// 8 independent loads in flight per batch (latency hiding).
// ---------------------------------------------------------------------------
__device__ __forceinline__ float eluf(float x) { return x > 0.0f ? x : expm1f(x); }

__device__ __forceinline__ void acc_h4(float4& acc, uint2 u) {
    float2 f0 = __half22float2(*(const __half2*)&u.x);
    float2 f1 = __half22float2(*(const __half2*)&u.y);
    acc.x += f0.x; acc.y += f0.y; acc.z += f1.x; acc.w += f1.y;
}

__global__ __launch_bounds__(256) void k_gather(const __half* __restrict__ hp,
                                                const int* __restrict__ rowptr,
                                                const int* __restrict__ colv,
                                                const float* __restrict__ dinv,
                                                const float* __restrict__ b,
                                                float* __restrict__ outp, int n) {
    int d    = blockIdx.x * 8 + (threadIdx.x >> 5);
    int lane = threadIdx.x & 31;
    if (d >= n) return;

    const uint2* hp2 = (const uint2*)hp;   // 32 uint2 (= 4 halves each) per row

    int start = rowptr[d];
    int end   = rowptr[d + 1];

    float4 acc = make_float4(0.f, 0.f, 0.f, 0.f);
    acc_h4(acc, hp2[(size_t)d * 32 + lane]);   // self-loop

    for (int base = start; base < end; base += 32) {
        int cnt  = min(32, end - base);
        int sidx = (base + lane < end) ? colv[base + lane] : 0;
        for (int j0 = 0; j0 < cnt; j0 += 8) {
            int m = cnt - j0;                  // valid in this batch (1..8)
            int ss[8];
            uint2 u[8];
#pragma unroll
            for (int t = 0; t < 8; t++)
                ss[t] = __shfl_sync(0xffffffffu, sidx, j0 + t);
#pragma unroll
            for (int t = 0; t < 8; t++)
                u[t] = (t < m) ? hp2[(size_t)ss[t] * 32 + lane] : make_uint2(0u, 0u);
#pragma unroll
            for (int t = 0; t < 8; t++)
                acc_h4(acc, u[t]);             // +0.0 for padded slots
        }
    }

    float w = dinv[d];
    // lane owns cols [lane*4, lane*4+4)
    float4 bb = ((const float4*)b)[lane];
    acc.x = eluf(acc.x * w + bb.x);
    acc.y = eluf(acc.y * w + bb.y);
    acc.z = eluf(acc.z * w + bb.z);
    acc.w = eluf(acc.w * w + bb.w);
    ((float4*)outp)[(size_t)d * 32 + lane] = acc;
}

// ---------------------------------------------------------------------------
// Launch
// ---------------------------------------------------------------------------
extern "C" void kernel_launch(void* const* d_in, const int* in_sizes, int n_in,
                              void* d_out, int out_size) {
    const float* x  = (const float*)d_in[0];
    const int*   ei = (const int*)d_in[1];
    const float* W1 = (const float*)d_in[2];
    const float* b1 = (const float*)d_in[3];
    const float* W2 = (const float*)d_in[4];
    const float* b2 = (const float*)d_in[5];
    float* out = (float*)d_out;

    int N = in_sizes[0] / DD;
    int E = in_sizes[1] / 2;
    const int* src = ei;
    const int* dst = ei + E;

    float *dinv, *buf2;
    __half* hbuf;
    int *cnt, *rowptr, *cur, *col, *part;
    uint8_t* wb;
    cudaGetSymbolAddress((void**)&dinv, g_dinv);
    cudaGetSymbolAddress((void**)&hbuf, g_hbuf);
    cudaGetSymbolAddress((void**)&buf2, g_buf2);
    cudaGetSymbolAddress((void**)&cnt, g_cnt);
    cudaGetSymbolAddress((void**)&rowptr, g_rowptr);
    cudaGetSymbolAddress((void**)&cur, g_cur);
    cudaGetSymbolAddress((void**)&col, g_col);
    cudaGetSymbolAddress((void**)&part, g_part);
    cudaGetSymbolAddress((void**)&wb, g_wb);

    cudaFuncSetAttribute(k_gemm_mma, cudaFuncAttributeMaxDynamicSharedMemorySize,
                         GEMM_SMEM);

    const int T  = 256;
    int nb       = (N + 1023) / 1024;          // <= 64 partials
    int egrid4   = (E / 4 + T - 1) / T;

    // CSR build + normalization
    cudaMemsetAsync(cnt, 0, (size_t)N * sizeof(int));
    k_hist<<<egrid4, T>>>(dst, cnt, E);
    k_scan_partial<<<nb, T>>>(cnt, part, N);
    k_scan_down<<<nb, T>>>(cnt, part, rowptr, cur, dinv, N, nb);
    k_fill<<<egrid4, T>>>(src, dst, cur, col, E);

    int gemm_grid   = (N + 127) / 128;
    int gather_grid = (N + 7) / 8;

    // Layer 1
    k_wprep<<<64, 256>>>(W1, wb);
    k_gemm_mma<<<gemm_grid, 256, GEMM_SMEM>>>(x, wb, dinv, hbuf, N);
    k_gather<<<gather_grid, 256>>>(hbuf, rowptr, col, dinv, b1, buf2, N);

    // Layer 2
    k_wprep<<<64, 256>>>(W2, wb);
    k_gemm_mma<<<gemm_grid, 256, GEMM_SMEM>>>(buf2, wb, dinv, hbuf, N);
    k_gather<<<gather_grid, 256>>>(hbuf, rowptr, col, dinv, b2, out, N);
}

// round 9
// speedup vs baseline: 1.0847x; 1.0847x over previous
#include <cuda_runtime.h>
#include <cuda_bf16.h>
#include <cuda_fp16.h>
#include <math.h>
#include <stdint.h>

#define DD   128
#define MAXN 50000
#define MAXE 800000

// Scratch (allocation-free rule: __device__ globals)
__device__ __align__(16) float   g_dinv[MAXN];
__device__ __align__(16) __half  g_hbuf[(size_t)MAXN * DD];  // fp16 messages
__device__ __align__(16) float   g_buf2[(size_t)MAXN * DD];  // fp32 activation
__device__ __align__(16) int     g_cnt[MAXN];
__device__ __align__(16) int     g_rowptr[MAXN + 4];
__device__ __align__(16) int     g_cur[MAXN];
__device__ __align__(16) int     g_col[MAXE];
__device__ __align__(16) int     g_part[64];
// Pre-split/transposed/swizzled W images (one per layer):
// [kh0: Bhi 16KB | Blo 16KB][kh1: Bhi 16KB | Blo 16KB]  (Bt[n][k] bf16, SW128)
__device__ __align__(16) uint8_t g_wb1[65536];
__device__ __align__(16) uint8_t g_wb2[65536];

// ---------------------------------------------------------------------------
// Helpers (sm_80+ only: ldmatrix + mma.sync — NO tcgen05, target is sm_103)
// ---------------------------------------------------------------------------
__device__ __forceinline__ uint32_t swz128(uint32_t off) {
    return off ^ ((off >> 3) & 0x70);
}
__device__ __forceinline__ uint32_t smem_u32(const void* p) {
    return (uint32_t)__cvta_generic_to_shared(p);
}

__device__ __forceinline__ void ldsm_x4(uint32_t& r0, uint32_t& r1,
                                        uint32_t& r2, uint32_t& r3, uint32_t addr) {
    asm volatile("ldmatrix.sync.aligned.m8n8.x4.shared.b16 {%0,%1,%2,%3}, [%4];"
                 : "=r"(r0), "=r"(r1), "=r"(r2), "=r"(r3) : "r"(addr));
}
__device__ __forceinline__ void ldsm_x2(uint32_t& r0, uint32_t& r1, uint32_t addr) {
    asm volatile("ldmatrix.sync.aligned.m8n8.x2.shared.b16 {%0,%1}, [%2];"
                 : "=r"(r0), "=r"(r1) : "r"(addr));
}
__device__ __forceinline__ void mma_bf16(float& d0, float& d1, float& d2, float& d3,
                                         uint32_t a0, uint32_t a1, uint32_t a2, uint32_t a3,
                                         uint32_t b0, uint32_t b1) {
    asm volatile(
        "mma.sync.aligned.m16n8k16.row.col.f32.bf16.bf16.f32 "
        "{%0,%1,%2,%3}, {%4,%5,%6,%7}, {%8,%9}, {%0,%1,%2,%3};"
        : "+f"(d0), "+f"(d1), "+f"(d2), "+f"(d3)
        : "r"(a0), "r"(a1), "r"(a2), "r"(a3), "r"(b0), "r"(b1));
}

// ---------------------------------------------------------------------------
// W split helper (shared by the fused hist+wprep kernel)
// ---------------------------------------------------------------------------
__device__ __forceinline__ void wprep_one(const float* __restrict__ W,
                                          uint8_t* __restrict__ wb, int idx) {
    int nn = idx & 127;           // output col -> Bt row
    int k  = idx >> 7;            // input dim  -> Bt col
    float v = W[k * DD + nn];
    __nv_bfloat16 hi = __float2bfloat16(v);
    __nv_bfloat16 lo = __float2bfloat16(v - __bfloat162float(hi));
    int half = k >> 6, kk = k & 63;
    uint32_t off = swz128((uint32_t)(nn * 128 + kk * 2));
    *(__nv_bfloat16*)(wb + half * 32768 + off)         = hi;
    *(__nv_bfloat16*)(wb + half * 32768 + 16384 + off) = lo;
}

// ---------------------------------------------------------------------------
// Fused: histogram of dst (blocks < eb) + W1/W2 prep (64 blocks each after)
// ---------------------------------------------------------------------------
__global__ void k_hist_wprep(const int* __restrict__ dst, int* __restrict__ cnt,
                             int E, int eb,
                             const float* __restrict__ W1, uint8_t* __restrict__ wb1,
                             const float* __restrict__ W2, uint8_t* __restrict__ wb2) {
    int b = blockIdx.x;
    if (b < eb) {
        int i = (b * blockDim.x + threadIdx.x) * 4;
        if (i + 3 < E && ((((size_t)dst) & 15) == 0)) {
            int4 d = *(const int4*)(dst + i);
            atomicAdd(&cnt[d.x], 1);
            atomicAdd(&cnt[d.y], 1);
            atomicAdd(&cnt[d.z], 1);
            atomicAdd(&cnt[d.w], 1);
        } else {
            for (int j = 0; j < 4; j++)
                if (i + j < E) atomicAdd(&cnt[dst[i + j]], 1);
        }
    } else if (b < eb + 64) {
        wprep_one(W1, wb1, (b - eb) * 256 + threadIdx.x);
    } else {
        wprep_one(W2, wb2, (b - eb - 64) * 256 + threadIdx.x);
    }
}

// ---------------------------------------------------------------------------
// 2-phase exclusive scan (+ dinv epilogue). Phase 1: per-block (1024) sums.
// ---------------------------------------------------------------------------
__global__ __launch_bounds__(256) void k_scan_partial(const int* __restrict__ cnt,
                                                      int* __restrict__ part, int n) {
    __shared__ int sh[8];
    int tid  = threadIdx.x;
    int base = blockIdx.x * 1024 + tid * 4;
    int s = 0;
    if (base + 3 < n) {
        int4 v = *(const int4*)(cnt + base);
        s = v.x + v.y + v.z + v.w;
    } else {
        for (int j = 0; j < 4; j++)
            if (base + j < n) s += cnt[base + j];
    }
#pragma unroll
    for (int o = 16; o; o >>= 1) s += __shfl_down_sync(0xffffffffu, s, o);
    if ((tid & 31) == 0) sh[tid >> 5] = s;
    __syncthreads();
    if (tid < 8) {
        s = sh[tid];
#pragma unroll
        for (int o = 4; o; o >>= 1) s += __shfl_down_sync(0x000000ffu, s, o);
        if (tid == 0) part[blockIdx.x] = s;
    }
}

// Phase 2 (fused tops-scan): every block redundantly scans the <=64 partials
// in-register, takes its own exclusive offset, then does the downsweep.
__global__ __launch_bounds__(256) void k_scan_down(const int* __restrict__ cnt,
                                                   const int* __restrict__ part,
                                                   int* __restrict__ rowptr,
                                                   int* __restrict__ cur,
                                                   float* __restrict__ dinv,
                                                   int n, int nb) {
    __shared__ int wsum[8];
    __shared__ int porig[64];
    __shared__ int pincl[64];
    int tid  = threadIdx.x;
    int lane = tid & 31, wid = tid >> 5;

    if (tid < 64) {
        int v = (tid < nb) ? part[tid] : 0;
        porig[tid] = v;
        int x = v;
#pragma unroll
        for (int o = 1; o < 32; o <<= 1) {
            int u = __shfl_up_sync(0xffffffffu, x, o);
            if (lane >= o) x += u;
        }
        pincl[tid] = x;
    }
    __syncthreads();
    int bi = blockIdx.x;
    int bincl = pincl[bi] + ((bi >= 32) ? pincl[31] : 0);
    int bexc  = bincl - porig[bi];
    if (bi == nb - 1 && tid == 0) rowptr[n] = bincl;

    int base = bi * 1024 + tid * 4;

    int4 c = make_int4(0, 0, 0, 0);
    if (base + 3 < n) c = *(const int4*)(cnt + base);
    else {
        int* cp = (int*)&c;
        for (int j = 0; j < 4; j++) cp[j] = (base + j < n) ? cnt[base + j] : 0;
    }
    int s0 = c.x, s1 = s0 + c.y, s2 = s1 + c.z, s3 = s2 + c.w;
    int ts = s3, sc = ts;
#pragma unroll
    for (int o = 1; o < 32; o <<= 1) {
        int u = __shfl_up_sync(0xffffffffu, sc, o);
        if (lane >= o) sc += u;
    }
    if (lane == 31) wsum[wid] = sc;
    __syncthreads();
    if (wid == 0) {
        int w = (lane < 8) ? wsum[lane] : 0;
#pragma unroll
        for (int o = 1; o < 8; o <<= 1) {
            int u = __shfl_up_sync(0xffffffffu, w, o);
            if (lane >= o) w += u;
        }
        if (lane < 8) wsum[lane] = w;
    }
    __syncthreads();

    int off = bexc + (wid ? wsum[wid - 1] : 0) + (sc - ts);
    if (base + 3 < n) {
        int4 r = make_int4(off, off + s0, off + s1, off + s2);
        *(int4*)(rowptr + base) = r;
        *(int4*)(cur + base)    = r;
        float4 dv = make_float4(rsqrtf((float)(c.x + 1)), rsqrtf((float)(c.y + 1)),
                                rsqrtf((float)(c.z + 1)), rsqrtf((float)(c.w + 1)));
        *(float4*)(dinv + base) = dv;
    } else {
        int rr[4] = {off, off + s0, off + s1, off + s2};
        int* cp = (int*)&c;
        for (int j = 0; j < 4; j++)
            if (base + j < n) {
                rowptr[base + j] = rr[j];
                cur[base + j]    = rr[j];
                dinv[base + j]   = rsqrtf((float)(cp[j] + 1));
            }
    }
}

// ---------------------------------------------------------------------------
// CSR fill
// ---------------------------------------------------------------------------
__global__ void k_fill(const int* __restrict__ src, const int* __restrict__ dst,
                       int* __restrict__ cur, int* __restrict__ col, int E) {
    int i = (blockIdx.x * blockDim.x + threadIdx.x) * 4;
    if (i + 3 < E && ((((size_t)src) & 15) == 0) && ((((size_t)dst) & 15) == 0)) {
        int4 s = *(const int4*)(src + i);
        int4 d = *(const int4*)(dst + i);
        col[atomicAdd(&cur[d.x], 1)] = s.x;
        col[atomicAdd(&cur[d.y], 1)] = s.y;
        col[atomicAdd(&cur[d.z], 1)] = s.z;
        col[atomicAdd(&cur[d.w], 1)] = s.w;
    } else {
        for (int j = 0; j < 4; j++)
            if (i + j < E) col[atomicAdd(&cur[dst[i + j]], 1)] = src[i + j];
    }
}

// ---------------------------------------------------------------------------
// Tensor-core GEMM via mma.sync (split bf16, fp32 accum), fp16 output:
//   Ch[r,:] = (half) dinv[r] * (A[r,:] @ W)
// ---------------------------------------------------------------------------
static const uint32_t GEMM_SMEM = 65536;

__global__ void __launch_bounds__(256)
k_gemm_mma(const float* __restrict__ A, const uint8_t* __restrict__ wb,
           const float* __restrict__ dinv, __half* __restrict__ Ch, int n) {
    extern __shared__ char sm[];
    uint32_t sbase = smem_u32(sm);
    int tid  = threadIdx.x;
    int wid  = tid >> 5, lane = tid & 31;
    int row0 = blockIdx.x * 128;

    int mrow0 = (wid & 3) * 32;
    int ncol0 = (wid >> 2) * 64;

    float acc[2][8][4];
#pragma unroll
    for (int i = 0; i < 2; i++)
#pragma unroll
        for (int j = 0; j < 8; j++)
#pragma unroll
            for (int q = 0; q < 4; q++) acc[i][j][q] = 0.0f;

    const float4* A4 = (const float4*)A;

    for (int kh = 0; kh < 2; kh++) {
        const float4* wb4 = (const float4*)(wb + kh * 32768);
#pragma unroll
        for (int t = 0; t < 8; t++) {
            int i = tid + t * 256;
            *(float4*)(sm + 32768 + i * 16) = wb4[i];
        }
#pragma unroll
        for (int t = 0; t < 8; t++) {
            int i  = tid + t * 256;
            int m  = i >> 4;
            int f4 = i & 15;
            int gr = row0 + m;
            float4 v = (gr < n) ? A4[(size_t)gr * 32 + kh * 16 + f4]
                                : make_float4(0.f, 0.f, 0.f, 0.f);
            __nv_bfloat16 hx = __float2bfloat16(v.x);
            __nv_bfloat16 hy = __float2bfloat16(v.y);
            __nv_bfloat16 hz = __float2bfloat16(v.z);
            __nv_bfloat16 hw = __float2bfloat16(v.w);
            __nv_bfloat162 h0, h1, l0, l1;
            h0.x = hx; h0.y = hy; h1.x = hz; h1.y = hw;
            l0.x = __float2bfloat16(v.x - __bfloat162float(hx));
            l0.y = __float2bfloat16(v.y - __bfloat162float(hy));
            l1.x = __float2bfloat16(v.z - __bfloat162float(hz));
            l1.y = __float2bfloat16(v.w - __bfloat162float(hw));
            uint32_t off = swz128((uint32_t)(m * 128 + f4 * 8));
            *(__nv_bfloat162*)(sm + off)             = h0;
            *(__nv_bfloat162*)(sm + off + 4)         = h1;
            *(__nv_bfloat162*)(sm + 16384 + off)     = l0;
            *(__nv_bfloat162*)(sm + 16384 + off + 4) = l1;
        }
        __syncthreads();

#pragma unroll
        for (int k16 = 0; k16 < 4; k16++) {
            int kbyte = k16 * 32;
            uint32_t afh[2][4], afl[2][4];
#pragma unroll
            for (int mt = 0; mt < 2; mt++) {
                int mrow = mrow0 + mt * 16 + (lane & 7) + ((lane & 8) ? 8 : 0);
                int kb   = kbyte + ((lane & 16) ? 16 : 0);
                uint32_t a = sbase + swz128((uint32_t)(mrow * 128 + kb));
                ldsm_x4(afh[mt][0], afh[mt][1], afh[mt][2], afh[mt][3], a);
                ldsm_x4(afl[mt][0], afl[mt][1], afl[mt][2], afl[mt][3], a + 16384);
            }
#pragma unroll
            for (int nt = 0; nt < 8; nt++) {
                int nrow = ncol0 + nt * 8 + (lane & 7);
                int kb   = kbyte + ((lane & 8) ? 16 : 0);
                uint32_t baddr = sbase + 32768 + swz128((uint32_t)(nrow * 128 + kb));
                uint32_t bh0, bh1, bl0, bl1;
                ldsm_x2(bh0, bh1, baddr);
                ldsm_x2(bl0, bl1, baddr + 16384);
#pragma unroll
                for (int mt = 0; mt < 2; mt++) {
                    mma_bf16(acc[mt][nt][0], acc[mt][nt][1], acc[mt][nt][2], acc[mt][nt][3],
                             afh[mt][0], afh[mt][1], afh[mt][2], afh[mt][3], bh0, bh1);
                    mma_bf16(acc[mt][nt][0], acc[mt][nt][1], acc[mt][nt][2], acc[mt][nt][3],
                             afh[mt][0], afh[mt][1], afh[mt][2], afh[mt][3], bl0, bl1);
                    mma_bf16(acc[mt][nt][0], acc[mt][nt][1], acc[mt][nt][2], acc[mt][nt][3],
                             afl[mt][0], afl[mt][1], afl[mt][2], afl[mt][3], bh0, bh1);
                }
            }
        }
        __syncthreads();
    }

#pragma unroll
    for (int mt = 0; mt < 2; mt++) {
        int r1 = row0 + mrow0 + mt * 16 + (lane >> 2);
        int r2 = r1 + 8;
        float s1 = (r1 < n) ? dinv[r1] : 0.f;
        float s2 = (r2 < n) ? dinv[r2] : 0.f;
#pragma unroll
        for (int nt = 0; nt < 8; nt++) {
            int col = ncol0 + nt * 8 + ((lane & 3) << 1);
            if (r1 < n)
                *(__half2*)(Ch + (size_t)r1 * DD + col) =
                    __floats2half2_rn(acc[mt][nt][0] * s1, acc[mt][nt][1] * s1);
            if (r2 < n)
                *(__half2*)(Ch + (size_t)r2 * DD + col) =
                    __floats2half2_rn(acc[mt][nt][2] * s2, acc[mt][nt][3] * s2);
        }
    }
}

// ---------------------------------------------------------------------------
// Fused CSR gather + self-loop + bias + ELU.
// TWO nodes per warp: lanes 0-15 -> node 2w, lanes 16-31 -> node 2w+1.
// Lane owns a uint4 (8 halves = cols hl*8..hl*8+8). LDG.128 per edge.
// Half-warps iterate independently (split masks, shfl width 16).
// ---------------------------------------------------------------------------
__device__ __forceinline__ float eluf(float x) { return x > 0.0f ? x : expm1f(x); }

__device__ __forceinline__ void acc_h8(float4& a0, float4& a1, uint4 u) {
    float2 f0 = __half22float2(*(const __half2*)&u.x);
    float2 f1 = __half22float2(*(const __half2*)&u.y);
    float2 f2 = __half22float2(*(const __half2*)&u.z);
    float2 f3 = __half22float2(*(const __half2*)&u.w);
    a0.x += f0.x; a0.y += f0.y; a0.z += f1.x; a0.w += f1.y;
    a1.x += f2.x; a1.y += f2.y; a1.z += f3.x; a1.w += f3.y;
}

__global__ __launch_bounds__(256) void k_gather(const __half* __restrict__ hp,
                                                const int* __restrict__ rowptr,
                                                const int* __restrict__ colv,
                                                const float* __restrict__ dinv,
                                                const float* __restrict__ b,
                                                float* __restrict__ outp, int n) {
    int lane = threadIdx.x & 31;
    int half = lane >> 4;
    int hl   = lane & 15;
    int d    = (blockIdx.x * 8 + (threadIdx.x >> 5)) * 2 + half;
    uint32_t hmask = half ? 0xFFFF0000u : 0x0000FFFFu;

    bool valid = d < n;
    int dd     = valid ? d : 0;

    const uint4* hp4 = (const uint4*)hp;   // 16 uint4 (8 halves each) per row

    int start = rowptr[dd];
    int end   = valid ? rowptr[dd + 1] : start;

    float4 a0 = make_float4(0.f, 0.f, 0.f, 0.f);
    float4 a1 = make_float4(0.f, 0.f, 0.f, 0.f);
    acc_h8(a0, a1, hp4[(size_t)dd * 16 + hl]);   // self-loop

    for (int base = start; base < end; base += 16) {
        int cnt  = min(16, end - base);
        int sidx = (base + hl < end) ? colv[base + hl] : 0;
        int j = 0;
        for (; j + 4 <= cnt; j += 4) {
            int s0 = __shfl_sync(hmask, sidx, j,     16);
            int s1 = __shfl_sync(hmask, sidx, j + 1, 16);
            int s2 = __shfl_sync(hmask, sidx, j + 2, 16);
            int s3 = __shfl_sync(hmask, sidx, j + 3, 16);
            uint4 u0 = hp4[(size_t)s0 * 16 + hl];
            uint4 u1 = hp4[(size_t)s1 * 16 + hl];
            uint4 u2 = hp4[(size_t)s2 * 16 + hl];
            uint4 u3 = hp4[(size_t)s3 * 16 + hl];
            acc_h8(a0, a1, u0);
            acc_h8(a0, a1, u1);
            acc_h8(a0, a1, u2);
            acc_h8(a0, a1, u3);
        }
        for (; j < cnt; j++) {
            int s = __shfl_sync(hmask, sidx, j, 16);
            acc_h8(a0, a1, hp4[(size_t)s * 16 + hl]);
        }
    }

    if (valid) {
        float w = dinv[dd];
        // lane owns cols [hl*8, hl*8+8)
        float4 b0 = ((const float4*)b)[hl * 2];
        float4 b1 = ((const float4*)b)[hl * 2 + 1];
        a0.x = eluf(a0.x * w + b0.x);
        a0.y = eluf(a0.y * w + b0.y);
        a0.z = eluf(a0.z * w + b0.z);
        a0.w = eluf(a0.w * w + b0.w);
        a1.x = eluf(a1.x * w + b1.x);
        a1.y = eluf(a1.y * w + b1.y);
        a1.z = eluf(a1.z * w + b1.z);
        a1.w = eluf(a1.w * w + b1.w);
        ((float4*)outp)[(size_t)dd * 32 + hl * 2]     = a0;
        ((float4*)outp)[(size_t)dd * 32 + hl * 2 + 1] = a1;
    }
}

// ---------------------------------------------------------------------------
// Launch
// ---------------------------------------------------------------------------
extern "C" void kernel_launch(void* const* d_in, const int* in_sizes, int n_in,
                              void* d_out, int out_size) {
    const float* x  = (const float*)d_in[0];
    const int*   ei = (const int*)d_in[1];
    const float* W1 = (const float*)d_in[2];
    const float* b1 = (const float*)d_in[3];
    const float* W2 = (const float*)d_in[4];
    const float* b2 = (const float*)d_in[5];
    float* out = (float*)d_out;

    int N = in_sizes[0] / DD;
    int E = in_sizes[1] / 2;
    const int* src = ei;
    const int* dst = ei + E;

    float *dinv, *buf2;
    __half* hbuf;
    int *cnt, *rowptr, *cur, *col, *part;
    uint8_t *wb1, *wb2;
    cudaGetSymbolAddress((void**)&dinv, g_dinv);
    cudaGetSymbolAddress((void**)&hbuf, g_hbuf);
    cudaGetSymbolAddress((void**)&buf2, g_buf2);
    cudaGetSymbolAddress((void**)&cnt, g_cnt);
    cudaGetSymbolAddress((void**)&rowptr, g_rowptr);
    cudaGetSymbolAddress((void**)&cur, g_cur);
    cudaGetSymbolAddress((void**)&col, g_col);
    cudaGetSymbolAddress((void**)&part, g_part);
    cudaGetSymbolAddress((void**)&wb1, g_wb1);
    cudaGetSymbolAddress((void**)&wb2, g_wb2);

    cudaFuncSetAttribute(k_gemm_mma, cudaFuncAttributeMaxDynamicSharedMemorySize,
                         GEMM_SMEM);

    const int T  = 256;
    int nb       = (N + 1023) / 1024;          // <= 64 partials
    int egrid4   = (E / 4 + T - 1) / T;

    // CSR build + normalization (+ fused W prep)
    cudaMemsetAsync(cnt, 0, (size_t)N * sizeof(int));
    k_hist_wprep<<<egrid4 + 128, T>>>(dst, cnt, E, egrid4, W1, wb1, W2, wb2);
    k_scan_partial<<<nb, T>>>(cnt, part, N);
    k_scan_down<<<nb, T>>>(cnt, part, rowptr, cur, dinv, N, nb);
    k_fill<<<egrid4, T>>>(src, dst, cur, col, E);

    int gemm_grid   = (N + 127) / 128;
    int gather_grid = (N + 15) / 16;   // 8 warps/block, 2 nodes/warp

    // Layer 1
    k_gemm_mma<<<gemm_grid, 256, GEMM_SMEM>>>(x, wb1, dinv, hbuf, N);
    k_gather<<<gather_grid, 256>>>(hbuf, rowptr, col, dinv, b1, buf2, N);

    // Layer 2
    k_gemm_mma<<<gemm_grid, 256, GEMM_SMEM>>>(buf2, wb2, dinv, hbuf, N);
    k_gather<<<gather_grid, 256>>>(hbuf, rowptr, col, dinv, b2, out, N);
}